// round 2
// baseline (speedup 1.0000x reference)
#include <cuda_runtime.h>
#include <cstdint>

#define MAX_SEG 100001

// scratch (no cudaMalloc allowed)
__device__ int g_offsets[MAX_SEG + 1];

// ---------------------------------------------------------------------------
// Inline dtype detection (reference declares int64; JAX w/o x64 emits int32).
// For little-endian int64 indices in [0, 2^31), every odd int32 word of the
// buffer is 0. For int32 data those words are uniform random gather indices;
// P(first 8 all zero) ~ (5e-6)^8 ~ 1e-42. One 32B-sector broadcast load per
// warp (L1-hot after first touch) + one vote.
// ---------------------------------------------------------------------------
__device__ __forceinline__ bool detect_is64_warp(const void* gidx, int lane) {
    const int* p = (const int*)gidx;
    int w = (lane < 8) ? p[2 * lane + 1] : 0;
    return __all_sync(0xFFFFFFFFu, w == 0);
}

__device__ __forceinline__ long long load_idx(const void* p, int i, bool is64) {
    return is64 ? ((const long long*)p)[i] : (long long)((const int*)p)[i];
}

// ---------------------------------------------------------------------------
// CSR offsets from sorted segment ids. offsets[s] = first edge with seg >= s.
// ---------------------------------------------------------------------------
__global__ void build_offsets_kernel(const void* __restrict__ seg,
                                     const void* __restrict__ gidx,
                                     int E, int nseg) {
    int e = blockIdx.x * blockDim.x + threadIdx.x;
    bool is64 = detect_is64_warp(gidx, threadIdx.x & 31);
    if (e >= E) return;
    int cur = (int)load_idx(seg, e, is64);
    int prev = (e == 0) ? -1 : (int)load_idx(seg, e - 1, is64);
    for (int s = prev + 1; s <= cur; s++) g_offsets[s] = e;
    if (e == E - 1) {
        for (int s = cur + 1; s <= nseg; s++) g_offsets[s] = E;
    }
}

// ---------------------------------------------------------------------------
// One warp per segment. Lanes 0-15 take even edges, lanes 16-31 odd edges;
// each lane reads a float4 slice of the 256B row (LDG.128, 16 lanes/row).
// Unroll x4 per half-warp -> 8 independent row gathers in flight per warp
// to cover ~250cyc L2 latency. Cross-half combine via shfl_xor(16).
// ---------------------------------------------------------------------------
__global__ void seg_mean_kernel(const float* __restrict__ values,
                                const void* __restrict__ gidx,
                                float* __restrict__ out, int nseg) {
    int lane = threadIdx.x & 31;
    bool is64 = detect_is64_warp(gidx, lane);

    int warp = (blockIdx.x * blockDim.x + threadIdx.x) >> 5;
    if (warp >= nseg) return;

    int half = lane >> 4;       // 0: even edges, 1: odd edges
    int l16  = lane & 15;       // float4 slot within row

    int start = g_offsets[warp];
    int end   = g_offsets[warp + 1];

    float4 a0 = {0.f, 0.f, 0.f, 0.f};
    float4 a1 = {0.f, 0.f, 0.f, 0.f};
    float4 a2 = {0.f, 0.f, 0.f, 0.f};
    float4 a3 = {0.f, 0.f, 0.f, 0.f};

    int e = start + half;
    // main loop: this half-warp consumes e, e+2, e+4, e+6 per iteration
    for (; e + 6 < end; e += 8) {
        long long i0 = load_idx(gidx, e + 0, is64);
        long long i1 = load_idx(gidx, e + 2, is64);
        long long i2 = load_idx(gidx, e + 4, is64);
        long long i3 = load_idx(gidx, e + 6, is64);
        float4 v0 = ((const float4*)(values + i0 * 64))[l16];
        float4 v1 = ((const float4*)(values + i1 * 64))[l16];
        float4 v2 = ((const float4*)(values + i2 * 64))[l16];
        float4 v3 = ((const float4*)(values + i3 * 64))[l16];
        a0.x += v0.x; a0.y += v0.y; a0.z += v0.z; a0.w += v0.w;
        a1.x += v1.x; a1.y += v1.y; a1.z += v1.z; a1.w += v1.w;
        a2.x += v2.x; a2.y += v2.y; a2.z += v2.z; a2.w += v2.w;
        a3.x += v3.x; a3.y += v3.y; a3.z += v3.z; a3.w += v3.w;
    }
    for (; e < end; e += 2) {
        long long i0 = load_idx(gidx, e, is64);
        float4 v0 = ((const float4*)(values + i0 * 64))[l16];
        a0.x += v0.x; a0.y += v0.y; a0.z += v0.z; a0.w += v0.w;
    }

    float sx = (a0.x + a1.x) + (a2.x + a3.x);
    float sy = (a0.y + a1.y) + (a2.y + a3.y);
    float sz = (a0.z + a1.z) + (a2.z + a3.z);
    float sw = (a0.w + a1.w) + (a2.w + a3.w);

    // combine the two half-warp partial sums (same l16 slot, xor lane bit 4)
    sx += __shfl_xor_sync(0xFFFFFFFFu, sx, 16);
    sy += __shfl_xor_sync(0xFFFFFFFFu, sy, 16);
    sz += __shfl_xor_sync(0xFFFFFFFFu, sz, 16);
    sw += __shfl_xor_sync(0xFFFFFFFFu, sw, 16);

    int cnt = end - start;
    float inv = 1.0f / (float)(cnt > 0 ? cnt : 1);

    if (half == 0) {
        float4 r = {sx * inv, sy * inv, sz * inv, sw * inv};
        ((float4*)(out + (long long)warp * 64))[l16] = r;
    }
}

// ---------------------------------------------------------------------------
// launch
// inputs: 0=values [N_SRC,64] f32, 1=gather_idx [E] i64/i32,
//         2=segment_ids [E] i64/i32 (sorted), 3=num_segments (scalar, unused)
// out: [nseg,64] f32, nseg = out_size/64
// ---------------------------------------------------------------------------
extern "C" void kernel_launch(void* const* d_in, const int* in_sizes, int n_in,
                              void* d_out, int out_size) {
    const float* values = (const float*)d_in[0];
    const void*  gidx   = d_in[1];
    const void*  seg    = d_in[2];
    float* out = (float*)d_out;

    int E    = in_sizes[1];
    int nseg = out_size / 64;
    if (nseg > MAX_SEG) nseg = MAX_SEG;

    int threads = 256;
    build_offsets_kernel<<<(E + threads - 1) / threads, threads>>>(seg, gidx, E, nseg);

    int warps_per_block = threads / 32;
    int blocks = (nseg + warps_per_block - 1) / warps_per_block;
    seg_mean_kernel<<<blocks, threads>>>(values, gidx, out, nseg);
}

// round 3
// speedup vs baseline: 1.3588x; 1.3588x over previous
#include <cuda_runtime.h>
#include <cstdint>

#define MAX_SEG 100001

// scratch (no cudaMalloc allowed)
__device__ int g_offsets[MAX_SEG + 1];

// ---------------------------------------------------------------------------
// Inline dtype detection (reference declares int64; JAX w/o x64 emits int32).
// For little-endian int64 indices in [0, 2^31), every odd int32 word is 0.
// For int32 data those words are uniform random gather indices;
// P(first 8 all zero) ~ 1e-42. One broadcast sector load + one vote.
// ---------------------------------------------------------------------------
__device__ __forceinline__ bool detect_is64_warp(const void* gidx, int lane) {
    const int* p = (const int*)gidx;
    int w = (lane < 8) ? p[2 * lane + 1] : 0;
    return __all_sync(0xFFFFFFFFu, w == 0);
}

__device__ __forceinline__ long long load_idx(const void* p, int i, bool is64) {
    return is64 ? ((const long long*)p)[i] : (long long)((const int*)p)[i];
}

// ---------------------------------------------------------------------------
// CSR offsets from sorted segment ids. offsets[s] = first edge with seg >= s.
// ---------------------------------------------------------------------------
__global__ void build_offsets_kernel(const void* __restrict__ seg,
                                     const void* __restrict__ gidx,
                                     int E, int nseg) {
    int e = blockIdx.x * blockDim.x + threadIdx.x;
    bool is64 = detect_is64_warp(gidx, threadIdx.x & 31);
    if (e >= E) return;
    int cur = (int)load_idx(seg, e, is64);
    int prev = (e == 0) ? -1 : (int)load_idx(seg, e - 1, is64);
    for (int s = prev + 1; s <= cur; s++) g_offsets[s] = e;
    if (e == E - 1) {
        for (int s = cur + 1; s <= nseg; s++) g_offsets[s] = E;
    }
}

// ---------------------------------------------------------------------------
// One warp per segment, lane owns a float2 slice of the 256B row.
// Key trick: the warp first loads up to 32 of the segment's gather indices
// with ONE coalesced load (gidx[start+lane]); the row loop then obtains its
// index via __shfl_sync -> the idx->row memory dependency chain is gone and
// all row gathers of a 32-edge chunk are mutually independent. 4 accumulators
// keep >= 4 row reads (1KB) in flight per warp at all times.
// ---------------------------------------------------------------------------
__global__ void __launch_bounds__(128)
seg_mean_kernel(const float* __restrict__ values,
                const void* __restrict__ gidx,
                float* __restrict__ out, int nseg) {
    int lane = threadIdx.x & 31;
    bool is64 = detect_is64_warp(gidx, lane);

    int warp = (blockIdx.x * blockDim.x + threadIdx.x) >> 5;
    if (warp >= nseg) return;

    int start = g_offsets[warp];
    int end   = g_offsets[warp + 1];

    float2 a0 = {0.f, 0.f}, a1 = {0.f, 0.f}, a2 = {0.f, 0.f}, a3 = {0.f, 0.f};

    for (int base = start; base < end; base += 32) {
        int n = end - base;
        if (n > 32) n = 32;
        // one coalesced load of up to 32 indices for this chunk
        int myidx = 0;
        if (lane < n) myidx = (int)load_idx(gidx, base + lane, is64);

        int j = 0;
        for (; j + 4 <= n; j += 4) {
            int i0 = __shfl_sync(0xFFFFFFFFu, myidx, j + 0);
            int i1 = __shfl_sync(0xFFFFFFFFu, myidx, j + 1);
            int i2 = __shfl_sync(0xFFFFFFFFu, myidx, j + 2);
            int i3 = __shfl_sync(0xFFFFFFFFu, myidx, j + 3);
            float2 v0 = ((const float2*)(values + (long long)i0 * 64))[lane];
            float2 v1 = ((const float2*)(values + (long long)i1 * 64))[lane];
            float2 v2 = ((const float2*)(values + (long long)i2 * 64))[lane];
            float2 v3 = ((const float2*)(values + (long long)i3 * 64))[lane];
            a0.x += v0.x; a0.y += v0.y;
            a1.x += v1.x; a1.y += v1.y;
            a2.x += v2.x; a2.y += v2.y;
            a3.x += v3.x; a3.y += v3.y;
        }
        for (; j < n; j++) {
            int i0 = __shfl_sync(0xFFFFFFFFu, myidx, j);
            float2 v0 = ((const float2*)(values + (long long)i0 * 64))[lane];
            a0.x += v0.x; a0.y += v0.y;
        }
    }

    float sx = (a0.x + a1.x) + (a2.x + a3.x);
    float sy = (a0.y + a1.y) + (a2.y + a3.y);

    int cnt = end - start;
    float inv = 1.0f / (float)(cnt > 0 ? cnt : 1);
    float2 r = {sx * inv, sy * inv};
    ((float2*)(out + (long long)warp * 64))[lane] = r;
}

// ---------------------------------------------------------------------------
// launch
// inputs: 0=values [N_SRC,64] f32, 1=gather_idx [E] i64/i32,
//         2=segment_ids [E] i64/i32 (sorted), 3=num_segments (scalar, unused)
// out: [nseg,64] f32, nseg = out_size/64
// ---------------------------------------------------------------------------
extern "C" void kernel_launch(void* const* d_in, const int* in_sizes, int n_in,
                              void* d_out, int out_size) {
    const float* values = (const float*)d_in[0];
    const void*  gidx   = d_in[1];
    const void*  seg    = d_in[2];
    float* out = (float*)d_out;

    int E    = in_sizes[1];
    int nseg = out_size / 64;
    if (nseg > MAX_SEG) nseg = MAX_SEG;

    int bthreads = 256;
    build_offsets_kernel<<<(E + bthreads - 1) / bthreads, bthreads>>>(seg, gidx, E, nseg);

    int threads = 128;
    int warps_per_block = threads / 32;
    int blocks = (nseg + warps_per_block - 1) / warps_per_block;
    seg_mean_kernel<<<blocks, threads>>>(values, gidx, out, nseg);
}